// round 11
// baseline (speedup 1.0000x reference)
#include <cuda_runtime.h>

// ScorePredictor: 3x DistMult edge scoring.
// score[e] = clip( sum_d head[src[e],d] * rel[d] * tail[dst[e],d], 0, 1 )
//
// Structure (graph-capturable fork/join):
//   main stream : sort(ddi) -> score(ddi) -> score(dpi) -> score(ppi)
//   side stream : sort(dpi) ; sort(ppi)      [joined before score(dpi)]
// Score kernels are STRICTLY SEQUENTIAL in phase order — concurrent scores
// merge the 240MB working sets and thrash L2 (R10: 273->422us). Only the
// tiny sort kernels (int traffic) overlap with the first score phase.
//
// Score kernel (R7/R9 winner): warp handles 8 consecutive SORTED edges,
// k-chunk outer loop; rel chunk loaded once per k, head chunk (pre-multiplied
// by rel) reloaded only on key change, all 8 independent tail loads batched
// (MLP=8/warp). EPW=8 fits regs at __launch_bounds__(256,3); EPW=16 spills.

#define D_DIM 2048
#define WARPS_PER_BLOCK 8
#define THREADS_PER_BLOCK (WARPS_PER_BLOCK * 32)
#define EDGES_PER_WARP 8
#define EDGES_PER_BLOCK (WARPS_PER_BLOCK * EDGES_PER_WARP)

#define MAX_BINS 32768
#define MAX_E    131072

__device__ int  g_hist[3][MAX_BINS];
__device__ int4 g_edge[3][MAX_E];    // (key, other, edge, pad)

// ---------------- per-phase sort: zero / hist / scan / scatter ----------------

template <int P>
__global__ void zero_hist_p(int nbins) {
    int i = blockIdx.x * blockDim.x + threadIdx.x;
    if (i < nbins) g_hist[P][i] = 0;
}

template <int P>
__global__ void hist_p(const int* __restrict__ key, int E) {
    int i = blockIdx.x * blockDim.x + threadIdx.x;
    if (i < E) atomicAdd(&g_hist[P][__ldg(key + i)], 1);
}

template <int P>
__global__ void scan_p(int nbins) {
    int* h = g_hist[P];
    const int T = 1024;
    const int t = threadIdx.x;
    __shared__ int buf[2][1024];

    int chunk = (nbins + T - 1) / T;
    int start = t * chunk;
    int end   = min(start + chunk, nbins);

    int s = 0;
    for (int i = start; i < end; ++i) s += h[i];
    buf[0][t] = s;
    __syncthreads();

    int src = 0;
    for (int off = 1; off < T; off <<= 1) {
        int v = buf[src][t];
        if (t >= off) v += buf[src][t - off];
        buf[src ^ 1][t] = v;
        src ^= 1;
        __syncthreads();
    }

    int base = (t == 0) ? 0 : buf[src][t - 1];
    int run = base;
    for (int i = start; i < end; ++i) {
        int v = h[i];
        h[i] = run;
        run += v;
    }
}

template <int P>
__global__ void scatter_p(const int* __restrict__ key,
                          const int* __restrict__ other, int E) {
    int i = blockIdx.x * blockDim.x + threadIdx.x;
    if (i >= E) return;
    int k = __ldg(key + i);
    int o = __ldg(other + i);
    int pos = atomicAdd(&g_hist[P][k], 1);
    g_edge[P][pos] = make_int4(k, o, i, 0);
}

// ---------------- score ----------------

template <int P>
__global__ __launch_bounds__(THREADS_PER_BLOCK, 3)
void score_p(
    const float* __restrict__ xs,    // sorted-side table (heads)
    const float* __restrict__ xr,    // random-side table (tails)
    const float* __restrict__ rel,
    float*       __restrict__ o,
    int E)
{
    const int4* recs = g_edge[P];

    const int warp = threadIdx.x >> 5;
    const int lane = threadIdx.x & 31;
    const int base = (blockIdx.x * WARPS_PER_BLOCK + warp) * EDGES_PER_WARP;
    if (base >= E) return;

    // Lanes 0..7 fetch packed edge records; broadcast via shuffles.
    int pos = base + lane;
    if (pos >= E) pos = E - 1;              // duplicate last edge (same output)
    int my_s = 0, my_d = 0, my_edge = 0;
    if (lane < EDGES_PER_WARP) {
        int4 r = __ldg(recs + pos);
        my_s = r.x; my_d = r.y; my_edge = r.z;
    }

    int s[EDGES_PER_WARP], dI[EDGES_PER_WARP];
    #pragma unroll
    for (int e = 0; e < EDGES_PER_WARP; ++e) {
        s[e]  = __shfl_sync(0xffffffffu, my_s, e);
        dI[e] = __shfl_sync(0xffffffffu, my_d, e);
    }

    float acc[EDGES_PER_WARP];
    #pragma unroll
    for (int e = 0; e < EDGES_PER_WARP; ++e) acc[e] = 0.0f;

    // 16 k-chunks of float4 per lane. Batch all 8 independent tail loads
    // before the FMA block so ptxas issues them back-to-back (MLP=8).
    #pragma unroll 2
    for (int k = 0; k < D_DIM / (32 * 4); ++k) {
        const int idx = (k * 32 + lane) * 4;

        float4 t[EDGES_PER_WARP];
        #pragma unroll
        for (int e = 0; e < EDGES_PER_WARP; ++e)
            t[e] = __ldg(reinterpret_cast<const float4*>(
                       xr + (size_t)dI[e] * D_DIM + idx));

        const float4 r = __ldg(reinterpret_cast<const float4*>(rel + idx));

        float4 hr;   // head chunk pre-multiplied by rel; reload on key change
        #pragma unroll
        for (int e = 0; e < EDGES_PER_WARP; ++e) {
            if (e == 0 || s[e] != s[e - 1]) {   // warp-uniform branch
                float4 h = __ldg(reinterpret_cast<const float4*>(
                               xs + (size_t)s[e] * D_DIM + idx));
                hr.x = h.x * r.x; hr.y = h.y * r.y;
                hr.z = h.z * r.z; hr.w = h.w * r.w;
            }
            acc[e] = fmaf(hr.x, t[e].x, acc[e]);
            acc[e] = fmaf(hr.y, t[e].y, acc[e]);
            acc[e] = fmaf(hr.z, t[e].z, acc[e]);
            acc[e] = fmaf(hr.w, t[e].w, acc[e]);
        }
    }

    // Reduce and write each edge's score.
    #pragma unroll
    for (int e = 0; e < EDGES_PER_WARP; ++e) {
        float a = acc[e];
        #pragma unroll
        for (int off = 16; off > 0; off >>= 1)
            a += __shfl_xor_sync(0xffffffffu, a, off);
        const int edge_e = __shfl_sync(0xffffffffu, my_edge, e);
        if (lane == 0)
            o[edge_e] = fminf(fmaxf(a, 0.0f), 1.0f);
    }
}

// ---------------- launch ----------------

static cudaStream_t g_side;
static cudaEvent_t  g_fork, g_side_done;

static bool g_init_streams() {
    cudaStreamCreateWithFlags(&g_side, cudaStreamNonBlocking);
    cudaEventCreateWithFlags(&g_fork, cudaEventDisableTiming);
    cudaEventCreateWithFlags(&g_side_done, cudaEventDisableTiming);
    return true;
}

template <int P>
static void run_sort(cudaStream_t st, const int* key, const int* other,
                     int E, int nbins)
{
    zero_hist_p<P><<<(nbins + 255) / 256, 256, 0, st>>>(nbins);
    hist_p<P><<<(E + 255) / 256, 256, 0, st>>>(key, E);
    scan_p<P><<<1, 1024, 0, st>>>(nbins);
    scatter_p<P><<<(E + 255) / 256, 256, 0, st>>>(key, other, E);
}

extern "C" void kernel_launch(void* const* d_in, const int* in_sizes, int n_in,
                              void* d_out, int out_size)
{
    // Created once on the (uncaptured) correctness call; reused during capture.
    static bool inited = g_init_streams();
    (void)inited;

    const float* x_drug  = (const float*)d_in[0];
    const float* x_prot  = (const float*)d_in[1];
    const float* rel_ddi = (const float*)d_in[2];
    const float* rel_dpi = (const float*)d_in[3];
    const int*   ddi_src = (const int*)d_in[4];
    const int*   ddi_dst = (const int*)d_in[5];
    const int*   dpi_src = (const int*)d_in[6];
    const int*   dpi_dst = (const int*)d_in[7];
    const int*   ppi_src = (const int*)d_in[8];
    const int*   ppi_dst = (const int*)d_in[9];
    float* out = (float*)d_out;

    const int E      = in_sizes[4];
    const int N_DRUG = in_sizes[0] / D_DIM;
    const int N_PROT = in_sizes[1] / D_DIM;
    const int bpp    = (E + EDGES_PER_BLOCK - 1) / EDGES_PER_BLOCK;

    // Fork side stream off the main stream.
    cudaEventRecord(g_fork, 0);
    cudaStreamWaitEvent(g_side, g_fork, 0);

    // Side stream: dpi + ppi sorts (tiny int traffic), hidden under score 0.
    run_sort<1>(g_side, dpi_dst, dpi_src, E, N_PROT);
    run_sort<2>(g_side, ppi_src, ppi_dst, E, N_PROT);
    cudaEventRecord(g_side_done, g_side);

    // Main stream: ddi sort, then the three score phases sequentially.
    run_sort<0>(0, ddi_src, ddi_dst, E, N_DRUG);
    score_p<0><<<bpp, THREADS_PER_BLOCK>>>(x_drug, x_drug, rel_ddi, out, E);

    // Join: dpi/ppi edge records must be ready before their scores.
    cudaStreamWaitEvent(0, g_side_done, 0);

    score_p<1><<<bpp, THREADS_PER_BLOCK>>>(x_prot, x_drug, rel_dpi, out + E, E);
    score_p<2><<<bpp, THREADS_PER_BLOCK>>>(x_prot, x_prot, rel_dpi, out + 2 * E, E);
}